// round 2
// baseline (speedup 1.0000x reference)
#include <cuda_runtime.h>

// Problem constants (fixed by the dataset):
//   x: [8, 32, 512] fp32, w_q/w_k/w_v: [1, 128] fp32, out: [8, 32, 128] fp32
#define BV      256      // B*V rows
#define FDIM    512      // n_filters
#define DMODEL  128
#define CHUNKS  4        // f-chunks per row (load balance: 1024 blocks over 148 SMs)
#define FC      128      // f per block
#define TPB     128

// Guaranteed single MUFU.EX2 regardless of fast-math flags.
__device__ __forceinline__ float ex2_approx(float a) {
    float r;
    asm("ex2.approx.ftz.f32 %0, %1;" : "=f"(r) : "f"(a));
    return r;
}

// Scratch for partial sums of s_f per (row, chunk). Fully overwritten every
// launch (no accumulation), so no zeroing kernel is needed.
__device__ float g_partial[BV * CHUNKS];

__global__ __launch_bounds__(TPB)
void attn_partial_kernel(const float* __restrict__ x,
                         const float* __restrict__ wq,
                         const float* __restrict__ wk)
{
    __shared__ __align__(16) float sx[FDIM];
    __shared__ float sA[TPB];
    __shared__ float sB[TPB];
    __shared__ float sC[TPB];
    __shared__ float sK, sMax, sMin;

    const int tid   = threadIdx.x;
    const int bv    = blockIdx.x >> 2;
    const int chunk = blockIdx.x & 3;
    const float* __restrict__ xr = x + bv * FDIM;

    // Stage the row into smem; track row max/min for O(F) softmax max.
    float lmax = -3.402823466e38f, lmin = 3.402823466e38f;
    #pragma unroll
    for (int i = 0; i < FDIM / TPB; i++) {
        float v = xr[tid + TPB * i];
        sx[tid + TPB * i] = v;
        lmax = fmaxf(lmax, v);
        lmin = fminf(lmin, v);
    }
    // c = (w_q . w_k) / sqrt(128); fold log2(e) so the inner loop uses exp2.
    float p = wq[tid] * wk[tid];
    sA[tid] = p; sB[tid] = lmax; sC[tid] = lmin;
    __syncthreads();
    #pragma unroll
    for (int s = 64; s > 0; s >>= 1) {
        if (tid < s) {
            sA[tid] += sA[tid + s];
            sB[tid]  = fmaxf(sB[tid], sB[tid + s]);
            sC[tid]  = fminf(sC[tid], sC[tid + s]);
        }
        __syncthreads();
    }
    if (tid == 0) {
        // log2(e) / sqrt(128)
        sK   = sA[0] * (1.4426950408889634f * 0.08838834764831845f);
        sMax = sB[0];
        sMin = sC[0];
    }
    __syncthreads();

    // One f per thread. Logit (exp2 domain): t2 * x_g - M, M = max_g(t2*x_g).
    const float xf = sx[chunk * FC + tid];
    const float t2 = sK * xf;
    const float M  = (t2 >= 0.0f) ? t2 * sMax : t2 * sMin;

    float s0 = 0.f, s1 = 0.f, s2 = 0.f, s3 = 0.f;
    float w0 = 0.f, w1 = 0.f, w2 = 0.f, w3 = 0.f;
    const float4* __restrict__ x4 = (const float4*)sx;
    #pragma unroll 8
    for (int g = 0; g < FDIM / 4; g++) {
        float4 v = x4[g];   // smem broadcast (all threads same address)
        float e0 = ex2_approx(fmaf(t2, v.x, -M));
        float e1 = ex2_approx(fmaf(t2, v.y, -M));
        float e2 = ex2_approx(fmaf(t2, v.z, -M));
        float e3 = ex2_approx(fmaf(t2, v.w, -M));
        s0 += e0; s1 += e1; s2 += e2; s3 += e3;
        w0 = fmaf(e0, v.x, w0);
        w1 = fmaf(e1, v.y, w1);
        w2 = fmaf(e2, v.z, w2);
        w3 = fmaf(e3, v.w, w3);
    }
    float sf = ((w0 + w1) + (w2 + w3)) / ((s0 + s1) + (s2 + s3));

    // Block-reduce sum of s_f over this chunk's 128 f values.
    __syncthreads();
    sA[tid] = sf;
    __syncthreads();
    #pragma unroll
    for (int s = 64; s > 0; s >>= 1) {
        if (tid < s) sA[tid] += sA[tid + s];
        __syncthreads();
    }
    if (tid == 0) g_partial[blockIdx.x] = sA[0];
}

__global__ void finalize_kernel(const float* __restrict__ wv,
                                float* __restrict__ out)
{
    int i = blockIdx.x * blockDim.x + threadIdx.x;
    if (i >= BV * DMODEL) return;
    int bv = i >> 7;           // / DMODEL
    int d  = i & (DMODEL - 1);
    float m = (g_partial[bv * 4 + 0] + g_partial[bv * 4 + 1] +
               g_partial[bv * 4 + 2] + g_partial[bv * 4 + 3]) * (1.0f / 512.0f);
    out[i] = m * wv[d];
}

extern "C" void kernel_launch(void* const* d_in, const int* in_sizes, int n_in,
                              void* d_out, int out_size)
{
    const float* x  = (const float*)d_in[0];
    const float* wq = (const float*)d_in[1];
    const float* wk = (const float*)d_in[2];
    const float* wv = (const float*)d_in[3];
    float* out = (float*)d_out;

    attn_partial_kernel<<<BV * CHUNKS, TPB>>>(x, wq, wk);
    finalize_kernel<<<(BV * DMODEL + 255) / 256, 256>>>(wv, out);
}

// round 3
// speedup vs baseline: 1.0381x; 1.0381x over previous
#include <cuda_runtime.h>
#include <cuda_fp16.h>

// x: [8,32,512] fp32, w_q/w_k/w_v: [1,128] fp32, out: [8,32,128] fp32
#define BV      256
#define FDIM    512
#define DMODEL  128
#define CHUNKS  4
#define FC      128
#define TPB     128

__device__ float    g_partial[BV * CHUNKS];
__device__ unsigned g_cnt[BV];          // zero-init; self-resetting per launch

// f16x2 exp2 — one MUFU instruction, two exps.
__device__ __forceinline__ __half2 ex2_h2(__half2 a) {
    unsigned r, u = *(unsigned*)&a;
    asm("ex2.approx.f16x2 %0, %1;" : "=r"(r) : "r"(u));
    return *(__half2*)&r;
}

__device__ __forceinline__ float ldcg(const float* p) {
    float v;
    asm volatile("ld.global.cg.f32 %0, [%1];" : "=f"(v) : "l"(p));
    return v;
}

__global__ __launch_bounds__(TPB)
void attn_fused_kernel(const float* __restrict__ x,
                       const float* __restrict__ wq,
                       const float* __restrict__ wk,
                       const float* __restrict__ wv,
                       float* __restrict__ out)
{
    __shared__ __align__(16) float   sx[FDIM];
    __shared__ __align__(4)  __half2 sxh[FDIM / 2];
    __shared__ float sA[TPB];
    __shared__ float sB[TPB];
    __shared__ float sC[TPB];
    __shared__ float sK, sMax, sMin;
    __shared__ int   sLast;

    const int tid   = threadIdx.x;
    const int bv    = blockIdx.x >> 2;
    const int chunk = blockIdx.x & 3;
    const float* __restrict__ xr = x + bv * FDIM;

    // Stage row into smem (fp32), track row max/min for O(F) softmax max.
    float lmax = -3.402823466e38f, lmin = 3.402823466e38f;
    #pragma unroll
    for (int i = 0; i < FDIM / TPB; i++) {
        float v = xr[tid + TPB * i];
        sx[tid + TPB * i] = v;
        lmax = fmaxf(lmax, v);
        lmin = fminf(lmin, v);
    }
    float p = wq[tid] * wk[tid];   // c = (wq.wk)/sqrt(128), exp2 domain below
    sA[tid] = p; sB[tid] = lmax; sC[tid] = lmin;
    __syncthreads();
    #pragma unroll
    for (int s = 64; s > 0; s >>= 1) {
        if (tid < s) {
            sA[tid] += sA[tid + s];
            sB[tid]  = fmaxf(sB[tid], sB[tid + s]);
            sC[tid]  = fminf(sC[tid], sC[tid + s]);
        }
        __syncthreads();
    }
    if (tid == 0) {
        sK   = sA[0] * (1.4426950408889634f * 0.08838834764831845f); // log2(e)/sqrt(128)
        sMax = sB[0];
        sMin = sC[0];
    }
    __syncthreads();

    // Build half2 copy of the row (for num accumulation in HFMA2).
    #pragma unroll
    for (int j = tid; j < FDIM / 2; j += TPB)
        sxh[j] = __floats2half2_rn(sx[2 * j], sx[2 * j + 1]);
    __syncthreads();

    // One f per thread. M = max_g(t2*x_g) in exp2 domain.
    const float xf = sx[chunk * FC + tid];
    const float t2 = sK * xf;
    const float M  = (t2 >= 0.0f) ? t2 * sMax : t2 * sMin;

    float den = 0.0f, num = 0.0f;
    const float4* __restrict__ x4 = (const float4*)sx;

    // 32 outer blocks of 16 g; accumulate in f16x2 inside, drain to fp32.
    #pragma unroll 2
    for (int blk = 0; blk < FDIM / 16; blk++) {
        __half2 dh = __float2half2_rn(0.0f);
        __half2 nh = __float2half2_rn(0.0f);
        #pragma unroll
        for (int j = 0; j < 4; j++) {
            float4 v = x4[blk * 4 + j];       // smem broadcast
            __half2 l01 = __floats2half2_rn(fmaf(t2, v.x, -M), fmaf(t2, v.y, -M));
            __half2 l23 = __floats2half2_rn(fmaf(t2, v.z, -M), fmaf(t2, v.w, -M));
            __half2 e01 = ex2_h2(l01);
            __half2 e23 = ex2_h2(l23);
            __half2 xh01 = sxh[blk * 8 + j * 2];
            __half2 xh23 = sxh[blk * 8 + j * 2 + 1];
            dh = __hadd2(dh, __hadd2(e01, e23));
            nh = __hfma2(e01, xh01, nh);
            nh = __hfma2(e23, xh23, nh);
        }
        float2 d2 = __half22float2(dh);
        float2 n2 = __half22float2(nh);
        den += d2.x + d2.y;
        num += n2.x + n2.y;
    }
    float sf = num / den;

    // Block-reduce sum of s_f over this chunk's 128 f values.
    __syncthreads();
    sA[tid] = sf;
    __syncthreads();
    #pragma unroll
    for (int s = 64; s > 0; s >>= 1) {
        if (tid < s) sA[tid] += sA[tid + s];
        __syncthreads();
    }

    // Fused finalize: last chunk-block of this row writes the output row.
    if (tid == 0) {
        g_partial[blockIdx.x] = sA[0];
        __threadfence();                              // release partial
        unsigned old = atomicAdd(&g_cnt[bv], 1u);
        sLast = (old == CHUNKS - 1);
        if (sLast) __threadfence();                   // acquire others' partials
    }
    __syncthreads();
    if (sLast) {
        float m = (ldcg(&g_partial[bv * 4 + 0]) + ldcg(&g_partial[bv * 4 + 1]) +
                   ldcg(&g_partial[bv * 4 + 2]) + ldcg(&g_partial[bv * 4 + 3]))
                  * (1.0f / 512.0f);
        out[bv * DMODEL + tid] = m * wv[tid];
        if (tid == 0) g_cnt[bv] = 0;                  // self-reset for next launch
    }
}

extern "C" void kernel_launch(void* const* d_in, const int* in_sizes, int n_in,
                              void* d_out, int out_size)
{
    const float* x  = (const float*)d_in[0];
    const float* wq = (const float*)d_in[1];
    const float* wk = (const float*)d_in[2];
    const float* wv = (const float*)d_in[3];
    float* out = (float*)d_out;

    attn_fused_kernel<<<BV * CHUNKS, TPB>>>(x, wq, wk, wv, out);
}

// round 4
// speedup vs baseline: 1.1385x; 1.0968x over previous
#include <cuda_runtime.h>
#include <cuda_fp16.h>

// x: [8,32,512] fp32, w_q/w_k/w_v: [1,128] fp32, out: [8,32,128] fp32
#define BV      256
#define FDIM    512
#define DMODEL  128
#define CHUNKS  4
#define FC      128
#define TPB     128

__device__ float    g_partial[BV * CHUNKS];
__device__ unsigned g_cnt[BV];          // zero-init; self-resetting per launch

__device__ __forceinline__ __half2 ex2_h2(__half2 a) {
    unsigned r, u = *(unsigned*)&a;
    asm("ex2.approx.f16x2 %0, %1;" : "=r"(r) : "r"(u));
    return *(__half2*)&r;
}
__device__ __forceinline__ float ldcg(const float* p) {
    float v;
    asm volatile("ld.global.cg.f32 %0, [%1];" : "=f"(v) : "l"(p));
    return v;
}

__global__ __launch_bounds__(TPB)
void attn_fused_kernel(const float* __restrict__ x,
                       const float* __restrict__ wq,
                       const float* __restrict__ wk,
                       const float* __restrict__ wv,
                       float* __restrict__ out)
{
    __shared__ __align__(16) float   sx[FDIM];
    __shared__ __align__(16) __half2 sdmax[FDIM / 2];  // half2(x - xmax)
    __shared__ __align__(16) __half2 sdmin[FDIM / 2];  // half2(x - xmin)
    __shared__ float sRed[12];
    __shared__ float sA[TPB];
    __shared__ float sK, sMax, sMin;
    __shared__ int   sLast;

    const int tid   = threadIdx.x;
    const int lane  = tid & 31;
    const int warp  = tid >> 5;
    const int bv    = blockIdx.x >> 2;
    const int chunk = blockIdx.x & 3;
    const float* __restrict__ xr = x + bv * FDIM;

    // Stage row into smem (fp32), track row max/min.
    float lmax = -3.402823466e38f, lmin = 3.402823466e38f;
    #pragma unroll
    for (int i = 0; i < FDIM / TPB; i++) {
        float v = xr[tid + TPB * i];
        sx[tid + TPB * i] = v;
        lmax = fmaxf(lmax, v);
        lmin = fminf(lmin, v);
    }
    float p = wq[tid] * wk[tid];
    #pragma unroll
    for (int s = 16; s > 0; s >>= 1) {
        p    += __shfl_xor_sync(~0u, p, s);
        lmax  = fmaxf(lmax, __shfl_xor_sync(~0u, lmax, s));
        lmin  = fminf(lmin, __shfl_xor_sync(~0u, lmin, s));
    }
    if (lane == 0) { sRed[warp] = p; sRed[4 + warp] = lmax; sRed[8 + warp] = lmin; }
    __syncthreads();
    if (tid == 0) {
        float P  = sRed[0] + sRed[1] + sRed[2] + sRed[3];
        float Mx = fmaxf(fmaxf(sRed[4], sRed[5]), fmaxf(sRed[6], sRed[7]));
        float Mn = fminf(fminf(sRed[8], sRed[9]), fminf(sRed[10], sRed[11]));
        sK   = P * (1.4426950408889634f * 0.08838834764831845f); // log2(e)/sqrt(128)
        sMax = Mx;
        sMin = Mn;
    }
    __syncthreads();
    const float xmax = sMax, xmin = sMin;

    // Precompute half2 deviation rows (exact fp32 subtract, then one rounding).
    #pragma unroll
    for (int j = tid; j < FDIM / 2; j += TPB) {
        float a = sx[2 * j], b = sx[2 * j + 1];
        sdmax[j] = __floats2half2_rn(a - xmax, b - xmax);
        sdmin[j] = __floats2half2_rn(a - xmin, b - xmin);
    }
    __syncthreads();

    // One f per thread. logit = t2*(x_g - x_ext), x_ext = xmax if t2>=0 else xmin.
    const float xf   = sx[chunk * FC + tid];
    const float t2   = sK * xf;
    const bool  pos  = (t2 >= 0.0f);
    const float xext = pos ? xmax : xmin;
    const uint4* __restrict__ d4 = (const uint4*)(pos ? sdmax : sdmin);
    const __half2 t2h = __float2half2_rn(t2);

    float den = 0.0f, nump = 0.0f;   // nump = sum e*d;  s_f = nump/den + xext
    #pragma unroll 4
    for (int blk = 0; blk < FDIM / 16; blk++) {
        uint4 a = d4[2 * blk];       // 8 half2 = 16 g values (smem broadcast)
        uint4 b = d4[2 * blk + 1];
        __half2 dv0 = *(__half2*)&a.x, dv1 = *(__half2*)&a.y;
        __half2 dv2 = *(__half2*)&a.z, dv3 = *(__half2*)&a.w;
        __half2 dv4 = *(__half2*)&b.x, dv5 = *(__half2*)&b.y;
        __half2 dv6 = *(__half2*)&b.z, dv7 = *(__half2*)&b.w;

        __half2 e0 = ex2_h2(__hmul2(t2h, dv0));
        __half2 e1 = ex2_h2(__hmul2(t2h, dv1));
        __half2 e2 = ex2_h2(__hmul2(t2h, dv2));
        __half2 e3 = ex2_h2(__hmul2(t2h, dv3));
        __half2 e4 = ex2_h2(__hmul2(t2h, dv4));
        __half2 e5 = ex2_h2(__hmul2(t2h, dv5));
        __half2 e6 = ex2_h2(__hmul2(t2h, dv6));
        __half2 e7 = ex2_h2(__hmul2(t2h, dv7));

        // Two independent accumulators each (4 terms deep) to bound f16 error.
        __half2 dh0 = __hadd2(__hadd2(e0, e1), __hadd2(e2, e3));
        __half2 dh1 = __hadd2(__hadd2(e4, e5), __hadd2(e6, e7));
        __half2 nh0 = __hmul2(e0, dv0);
        nh0 = __hfma2(e1, dv1, nh0);
        nh0 = __hfma2(e2, dv2, nh0);
        nh0 = __hfma2(e3, dv3, nh0);
        __half2 nh1 = __hmul2(e4, dv4);
        nh1 = __hfma2(e5, dv5, nh1);
        nh1 = __hfma2(e6, dv6, nh1);
        nh1 = __hfma2(e7, dv7, nh1);

        float2 dd0 = __half22float2(dh0), dd1 = __half22float2(dh1);
        float2 nn0 = __half22float2(nh0), nn1 = __half22float2(nh1);
        den  += (dd0.x + dd0.y) + (dd1.x + dd1.y);
        nump += (nn0.x + nn0.y) + (nn1.x + nn1.y);
    }
    float sf = nump / den + xext;

    // Block-reduce sum of s_f over this chunk's 128 f values.
    __syncthreads();
    sA[tid] = sf;
    __syncthreads();
    #pragma unroll
    for (int s = 64; s > 0; s >>= 1) {
        if (tid < s) sA[tid] += sA[tid + s];
        __syncthreads();
    }

    // Fused finalize: last chunk-block of this row writes the output row.
    if (tid == 0) {
        g_partial[blockIdx.x] = sA[0];
        __threadfence();
        unsigned old = atomicAdd(&g_cnt[bv], 1u);
        sLast = (old == CHUNKS - 1);
        if (sLast) __threadfence();
    }
    __syncthreads();
    if (sLast) {
        float m = (ldcg(&g_partial[bv * 4 + 0]) + ldcg(&g_partial[bv * 4 + 1]) +
                   ldcg(&g_partial[bv * 4 + 2]) + ldcg(&g_partial[bv * 4 + 3]))
                  * (1.0f / 512.0f);
        out[bv * DMODEL + tid] = m * wv[tid];
        if (tid == 0) g_cnt[bv] = 0;
    }
}

extern "C" void kernel_launch(void* const* d_in, const int* in_sizes, int n_in,
                              void* d_out, int out_size)
{
    const float* x  = (const float*)d_in[0];
    const float* wq = (const float*)d_in[1];
    const float* wk = (const float*)d_in[2];
    const float* wv = (const float*)d_in[3];
    float* out = (float*)d_out;

    attn_fused_kernel<<<BV * CHUNKS, TPB>>>(x, wq, wk, wv, out);
}